// round 3
// baseline (speedup 1.0000x reference)
#include <cuda_runtime.h>
#include <math.h>

// ---------------------------------------------------------------------------
// CrossAttention: B=4, Lq=Lk=2048, D=1024, H=16, DH=64
//   q = split(q_in @ Wq^T + bq); k = split(k_in @ Wk^T + bk); v = tanh(k_in @ Wv^T + bv)
//   logits = (q.k)*SCALE ; masked -> -10000 ; attn = softmax(logits/0.5)
//   topk: keep attn >= 205th largest per row
//   ctx = (attn @ v) * q ; out = ctx_flat @ Wo^T + bo
// Folding: stored logit = raw_dot * (SCALE*2) = raw*0.25, masked -> -20000.
// ---------------------------------------------------------------------------

#define NB   4
#define NH   16
#define LSEQ 2048
#define NDH  64
#define ND   1024
#define NBH  64           // NB*NH
#define TOPK 205          // ceil(2048*0.1)

// scratch (module-static device memory; allocation APIs are forbidden)
__device__ float g_q[8388608];        // [bh][2048][64]
__device__ float g_k[8388608];        // [bh][2048][64]
__device__ float g_v[8388608];        // [bh][2048][64]
__device__ float g_ctx[8388608];      // [B*Lq][1024]  (head-interleaved, gated by q)
__device__ float g_attn[268435456];   // [bh][2048][2048]  (1 GiB)

// ---- packed f32x2 helpers (sm_103a FFMA2 — only reachable via PTX) ----
__device__ __forceinline__ unsigned long long pk2(float lo, float hi) {
    unsigned long long r;
    asm("mov.b64 %0, {%1, %2};" : "=l"(r) : "f"(lo), "f"(hi));
    return r;
}
__device__ __forceinline__ void upk2(unsigned long long v, float &lo, float &hi) {
    asm("mov.b64 {%0, %1}, %2;" : "=f"(lo), "=f"(hi) : "l"(v));
}
__device__ __forceinline__ void fma2(unsigned long long &d,
                                     unsigned long long a, unsigned long long b) {
    asm("fma.rn.f32x2 %0, %1, %2, %3;" : "=l"(d) : "l"(a), "l"(b), "l"(d));
}

// ---------------------------------------------------------------------------
// Generic NT SGEMM: C[M,N] = A[M,K] @ W[N,K]^T + bias
// BM=128, BN=128, BK=16, 256 threads, 8x8 micro-tile (as 8x4 f32x2 pairs).
// mode 0: plain store to out[m*N + n]
// mode 1: split-head store  out[((b*16+h)*Lseq + l)*64 + dh]
// mode 2: split-head store with tanh
// Requires M%128==0, N%128==0, K%16==0 (true for all uses here).
// ---------------------------------------------------------------------------
__global__ void __launch_bounds__(256, 2)
sgemm_nt(const float* __restrict__ A, const float* __restrict__ W,
         const float* __restrict__ bias, float* __restrict__ outp,
         int M, int N, int K, int mode, int Lseq)
{
    __shared__ float As[16][132];
    __shared__ float Bs[16][132];

    const int tid  = threadIdx.x;
    const int m0   = blockIdx.y * 128;
    const int n0   = blockIdx.x * 128;
    const int ty   = tid >> 4;        // 0..15 -> rows ty*8..+7
    const int tx   = tid & 15;        // 0..15 -> cols tx*8..+7
    const int lrow = tid >> 1;        // 0..127
    const int lc   = (tid & 1) * 8;   // 0 or 8

    const float* Ap = A + (size_t)(m0 + lrow) * K + lc;
    const float* Wp = W + (size_t)(n0 + lrow) * K + lc;

    float4 a0 = *(const float4*)(Ap);
    float4 a1 = *(const float4*)(Ap + 4);
    float4 w0 = *(const float4*)(Wp);
    float4 w1 = *(const float4*)(Wp + 4);

    unsigned long long acc[8][4];
#pragma unroll
    for (int i = 0; i < 8; i++)
#pragma unroll
        for (int j = 0; j < 4; j++) acc[i][j] = 0ull;

    const int nch = K >> 4;
    for (int c = 0; c < nch; c++) {
        __syncthreads();
        As[lc+0][lrow]=a0.x; As[lc+1][lrow]=a0.y; As[lc+2][lrow]=a0.z; As[lc+3][lrow]=a0.w;
        As[lc+4][lrow]=a1.x; As[lc+5][lrow]=a1.y; As[lc+6][lrow]=a1.z; As[lc+7][lrow]=a1.w;
        Bs[lc+0][lrow]=w0.x; Bs[lc+1][lrow]=w0.y; Bs[lc+2][lrow]=w0.z; Bs[lc+3][lrow]=w0.w;
        Bs[lc+4][lrow]=w1.x; Bs[lc+5][lrow]=w1.y; Bs[lc+6][lrow]=w1.z; Bs[lc+7][lrow]=w1.w;
        __syncthreads();
        if (c + 1 < nch) {
            const float* ap = Ap + (c + 1) * 16;
            const float* wp = Wp + (c + 1) * 16;
            a0 = *(const float4*)ap;       a1 = *(const float4*)(ap + 4);
            w0 = *(const float4*)wp;       w1 = *(const float4*)(wp + 4);
        }
#pragma unroll
        for (int kk = 0; kk < 16; kk++) {
            const float4 af0 = *(const float4*)&As[kk][ty * 8];
            const float4 af1 = *(const float4*)&As[kk][ty * 8 + 4];
            const float4 bf0 = *(const float4*)&Bs[kk][tx * 8];
            const float4 bf1 = *(const float4*)&Bs[kk][tx * 8 + 4];
            const unsigned long long bp0 = pk2(bf0.x, bf0.y);
            const unsigned long long bp1 = pk2(bf0.z, bf0.w);
            const unsigned long long bp2 = pk2(bf1.x, bf1.y);
            const unsigned long long bp3 = pk2(bf1.z, bf1.w);
            const float av[8] = {af0.x, af0.y, af0.z, af0.w, af1.x, af1.y, af1.z, af1.w};
#pragma unroll
            for (int i = 0; i < 8; i++) {
                const unsigned long long ad = pk2(av[i], av[i]);
                fma2(acc[i][0], ad, bp0);
                fma2(acc[i][1], ad, bp1);
                fma2(acc[i][2], ad, bp2);
                fma2(acc[i][3], ad, bp3);
            }
        }
    }

#pragma unroll
    for (int i = 0; i < 8; i++) {
        const int m = m0 + ty * 8 + i;
#pragma unroll
        for (int j = 0; j < 4; j++) {
            float c0, c1;
            upk2(acc[i][j], c0, c1);
            const int n = n0 + tx * 8 + j * 2;
            c0 += bias[n];
            c1 += bias[n + 1];
            if (mode == 0) {
                outp[(size_t)m * N + n]     = c0;
                outp[(size_t)m * N + n + 1] = c1;
            } else {
                if (mode == 2) { c0 = tanhf(c0); c1 = tanhf(c1); }
                const int b = m / Lseq, l = m - b * Lseq;
                const int h = n >> 6, dh = n & 63;
                const size_t o = (((size_t)(b * NH + h)) * Lseq + l) * NDH + dh;
                outp[o]     = c0;
                outp[o + 1] = c1;
            }
        }
    }
}

// ---------------------------------------------------------------------------
// logits: per bh,  L[2048,2048] = q[2048,64] @ k[2048,64]^T ; scale+mask;
// writes pre-softmax logits (already /0.5 folded) into g_attn.
// ---------------------------------------------------------------------------
__global__ void __launch_bounds__(256, 2)
logits_kernel(const int* __restrict__ mask)
{
    __shared__ float As[16][132];
    __shared__ float Bs[16][132];

    const int tid  = threadIdx.x;
    const int bh   = blockIdx.z;
    const int m0   = blockIdx.y * 128;
    const int n0   = blockIdx.x * 128;
    const int ty   = tid >> 4;
    const int tx   = tid & 15;
    const int lrow = tid >> 1;
    const int lc   = (tid & 1) * 8;

    const float* Ap = g_q + (size_t)bh * LSEQ * NDH + (size_t)(m0 + lrow) * NDH + lc;
    const float* Wp = g_k + (size_t)bh * LSEQ * NDH + (size_t)(n0 + lrow) * NDH + lc;

    float4 a0 = *(const float4*)(Ap);
    float4 a1 = *(const float4*)(Ap + 4);
    float4 w0 = *(const float4*)(Wp);
    float4 w1 = *(const float4*)(Wp + 4);

    unsigned long long acc[8][4];
#pragma unroll
    for (int i = 0; i < 8; i++)
#pragma unroll
        for (int j = 0; j < 4; j++) acc[i][j] = 0ull;

#pragma unroll
    for (int c = 0; c < 4; c++) {
        __syncthreads();
        As[lc+0][lrow]=a0.x; As[lc+1][lrow]=a0.y; As[lc+2][lrow]=a0.z; As[lc+3][lrow]=a0.w;
        As[lc+4][lrow]=a1.x; As[lc+5][lrow]=a1.y; As[lc+6][lrow]=a1.z; As[lc+7][lrow]=a1.w;
        Bs[lc+0][lrow]=w0.x; Bs[lc+1][lrow]=w0.y; Bs[lc+2][lrow]=w0.z; Bs[lc+3][lrow]=w0.w;
        Bs[lc+4][lrow]=w1.x; Bs[lc+5][lrow]=w1.y; Bs[lc+6][lrow]=w1.z; Bs[lc+7][lrow]=w1.w;
        __syncthreads();
        if (c < 3) {
            const float* ap = Ap + (c + 1) * 16;
            const float* wp = Wp + (c + 1) * 16;
            a0 = *(const float4*)ap;   a1 = *(const float4*)(ap + 4);
            w0 = *(const float4*)wp;   w1 = *(const float4*)(wp + 4);
        }
#pragma unroll
        for (int kk = 0; kk < 16; kk++) {
            const float4 af0 = *(const float4*)&As[kk][ty * 8];
            const float4 af1 = *(const float4*)&As[kk][ty * 8 + 4];
            const float4 bf0 = *(const float4*)&Bs[kk][tx * 8];
            const float4 bf1 = *(const float4*)&Bs[kk][tx * 8 + 4];
            const unsigned long long bp0 = pk2(bf0.x, bf0.y);
            const unsigned long long bp1 = pk2(bf0.z, bf0.w);
            const unsigned long long bp2 = pk2(bf1.x, bf1.y);
            const unsigned long long bp3 = pk2(bf1.z, bf1.w);
            const float av[8] = {af0.x, af0.y, af0.z, af0.w, af1.x, af1.y, af1.z, af1.w};
#pragma unroll
            for (int i = 0; i < 8; i++) {
                const unsigned long long ad = pk2(av[i], av[i]);
                fma2(acc[i][0], ad, bp0);
                fma2(acc[i][1], ad, bp1);
                fma2(acc[i][2], ad, bp2);
                fma2(acc[i][3], ad, bp3);
            }
        }
    }

    const int b = bh >> 4;
    const int* mrow = mask + b * LSEQ;
#pragma unroll
    for (int i = 0; i < 8; i++) {
        const int m = m0 + ty * 8 + i;
        float* orow = g_attn + ((size_t)bh * LSEQ + m) * LSEQ;
#pragma unroll
        for (int j = 0; j < 4; j++) {
            float c0, c1;
            upk2(acc[i][j], c0, c1);
            const int n = n0 + tx * 8 + j * 2;
            orow[n]     = mrow[n]     ? -20000.0f : c0 * 0.25f;  // SCALE*2 = 0.25
            orow[n + 1] = mrow[n + 1] ? -20000.0f : c1 * 0.25f;
        }
    }
}

// ---------------------------------------------------------------------------
// softmax + exact top-k threshold mask, per row of g_attn (in place).
// One CTA per row; 4-pass MSD radix select on float bits (all values >= 0).
// ---------------------------------------------------------------------------
__global__ void __launch_bounds__(256)
softmax_topk_kernel()
{
    __shared__ float p[LSEQ];
    __shared__ float red[256];
    __shared__ unsigned int hist[256];
    __shared__ unsigned int s_pref;
    __shared__ int s_r;

    const int tid = threadIdx.x;
    float* g = g_attn + (size_t)blockIdx.x * LSEQ;

    float mx = -1e30f;
    for (int i = tid; i < LSEQ; i += 256) {
        const float v = g[i];
        p[i] = v;
        mx = fmaxf(mx, v);
    }
    red[tid] = mx;
    __syncthreads();
    for (int s = 128; s > 0; s >>= 1) {
        if (tid < s) red[tid] = fmaxf(red[tid], red[tid + s]);
        __syncthreads();
    }
    const float m = red[0];
    __syncthreads();

    float sum = 0.0f;
    for (int i = tid; i < LSEQ; i += 256) {
        const float e = expf(p[i] - m);
        p[i] = e;
        sum += e;
    }
    red[tid] = sum;
    __syncthreads();
    for (int s = 128; s > 0; s >>= 1) {
        if (tid < s) red[tid] += red[tid + s];
        __syncthreads();
    }
    const float inv = 1.0f / red[0];
    for (int i = tid; i < LSEQ; i += 256) p[i] *= inv;

    if (tid == 0) { s_pref = 0u; s_r = TOPK; }
    __syncthreads();

    const unsigned int pmasks[4] = {0u, 0xFF000000u, 0xFFFF0000u, 0xFFFFFF00u};
#pragma unroll
    for (int pass = 0; pass < 4; pass++) {
        const int shift = 24 - pass * 8;
        hist[tid] = 0u;
        __syncthreads();
        const unsigned int pmask = pmasks[pass];
        const unsigned int pref  = s_pref;
        for (int i = tid; i < LSEQ; i += 256) {
            const unsigned int u = __float_as_uint(p[i]);
            if ((u & pmask) == pref) atomicAdd(&hist[(u >> shift) & 255], 1u);
        }
        __syncthreads();
        if (tid == 0) {
            const int rr = s_r;
            unsigned int cum = 0;
            int d = 255;
            for (; d > 0; d--) {
                const unsigned int cc = hist[d];
                if (cum + cc >= (unsigned int)rr) break;
                cum += cc;
            }
            s_pref = pref | ((unsigned int)d << shift);
            s_r = rr - (int)cum;
        }
        __syncthreads();
    }

    const float thr = __uint_as_float(s_pref);
    for (int i = tid; i < LSEQ; i += 256) {
        const float v = p[i];
        g[i] = (v >= thr) ? v : 0.0f;
    }
}

// ---------------------------------------------------------------------------
// ctx: per bh, C[2048,64] = attn[2048,2048] @ v[2048,64]; epilogue *= q,
// stored head-interleaved into g_ctx[B*Lq, 1024].
// BM=128, BN=64, BK=16, 256 threads, 8x4 micro.
// ---------------------------------------------------------------------------
__global__ void __launch_bounds__(256, 2)
ctx_kernel()
{
    __shared__ float As[16][132];
    __shared__ float Bs[16][68];

    const int tid  = threadIdx.x;
    const int bh   = blockIdx.y;
    const int m0   = blockIdx.x * 128;
    const int ty   = tid >> 4;        // rows ty*8..+7
    const int tx   = tid & 15;        // cols tx*4..+3
    const int lrow = tid >> 1;
    const int lc   = (tid & 1) * 8;
    const int vkr  = tid >> 4;        // 0..15
    const int vc   = (tid & 15) * 4;  // 0..60

    const float* Ap = g_attn + ((size_t)bh * LSEQ + m0 + lrow) * LSEQ + lc;
    const float* Vp = g_v + (size_t)bh * LSEQ * NDH + (size_t)vkr * NDH + vc;

    float4 a0 = *(const float4*)(Ap);
    float4 a1 = *(const float4*)(Ap + 4);
    float4 b0 = *(const float4*)(Vp);

    unsigned long long acc[8][2];
#pragma unroll
    for (int i = 0; i < 8; i++) { acc[i][0] = 0ull; acc[i][1] = 0ull; }

    for (int c = 0; c < 128; c++) {
        __syncthreads();
        As[lc+0][lrow]=a0.x; As[lc+1][lrow]=a0.y; As[lc+2][lrow]=a0.z; As[lc+3][lrow]=a0.w;
        As[lc+4][lrow]=a1.x; As[lc+5][lrow]=a1.y; As[lc+6][lrow]=a1.z; As[lc+7][lrow]=a1.w;
        *(float4*)&Bs[vkr][vc] = b0;
        __syncthreads();
        if (c + 1 < 128) {
            const float* ap = Ap + (c + 1) * 16;
            a0 = *(const float4*)ap;
            a1 = *(const float4*)(ap + 4);
            b0 = *(const float4*)(Vp + (size_t)(c + 1) * 16 * NDH);
        }
#pragma unroll
        for (int kk = 0; kk < 16; kk++) {
            const float4 af0 = *(const float4*)&As[kk][ty * 8];
            const float4 af1 = *(const float4*)&As[kk][ty * 8 + 4];
            const float4 bf  = *(const float4*)&Bs[kk][tx * 4];
            const unsigned long long bp0 = pk2(bf.x, bf.y);
            const unsigned long long bp1 = pk2(bf.z, bf.w);
            const float av[8] = {af0.x, af0.y, af0.z, af0.w, af1.x, af1.y, af1.z, af1.w};
#pragma unroll
            for (int i = 0; i < 8; i++) {
                const unsigned long long ad = pk2(av[i], av[i]);
                fma2(acc[i][0], ad, bp0);
                fma2(acc[i][1], ad, bp1);
            }
        }
    }

    const int b = bh >> 4, h = bh & 15;
#pragma unroll
    for (int i = 0; i < 8; i++) {
        const int m = m0 + ty * 8 + i;
        const float* qrow = g_q + ((size_t)bh * LSEQ + m) * NDH;
        float* crow = g_ctx + ((size_t)(b * LSEQ + m)) * ND + h * NDH;
#pragma unroll
        for (int j = 0; j < 2; j++) {
            float c0, c1;
            upk2(acc[i][j], c0, c1);
            const int n = tx * 4 + j * 2;
            crow[n]     = c0 * qrow[n];
            crow[n + 1] = c1 * qrow[n + 1];
        }
    }
}

// ---------------------------------------------------------------------------
extern "C" void kernel_launch(void* const* d_in, const int* in_sizes, int n_in,
                              void* d_out, int out_size)
{
    const float* q_in = (const float*)d_in[0];
    const float* k_in = (const float*)d_in[1];
    const float* Wq   = (const float*)d_in[2];
    const float* bq   = (const float*)d_in[3];
    const float* Wk   = (const float*)d_in[4];
    const float* bk   = (const float*)d_in[5];
    const float* Wv   = (const float*)d_in[6];
    const float* bv   = (const float*)d_in[7];
    const float* Wo   = (const float*)d_in[8];
    const float* bo   = (const float*)d_in[9];
    const int*   mask = (const int*)d_in[10];
    float* out = (float*)d_out;

    void *pq = 0, *pk = 0, *pv = 0, *pctx = 0;
    cudaGetSymbolAddress(&pq, g_q);
    cudaGetSymbolAddress(&pk, g_k);
    cudaGetSymbolAddress(&pv, g_v);
    cudaGetSymbolAddress(&pctx, g_ctx);

    const dim3 thr(256);
    const dim3 gp(ND / 128, (NB * LSEQ) / 128);          // (8, 64)

    sgemm_nt<<<gp, thr>>>(q_in, Wq, bq, (float*)pq, NB * LSEQ, ND, ND, 1, LSEQ);
    sgemm_nt<<<gp, thr>>>(k_in, Wk, bk, (float*)pk, NB * LSEQ, ND, ND, 1, LSEQ);
    sgemm_nt<<<gp, thr>>>(k_in, Wv, bv, (float*)pv, NB * LSEQ, ND, ND, 2, LSEQ);

    const dim3 gl(LSEQ / 128, LSEQ / 128, NBH);          // (16, 16, 64)
    logits_kernel<<<gl, thr>>>(mask);

    softmax_topk_kernel<<<NBH * LSEQ, thr>>>();          // 131072 rows

    const dim3 gc(LSEQ / 128, NBH);                      // (16, 64)
    ctx_kernel<<<gc, thr>>>();

    sgemm_nt<<<gp, thr>>>((const float*)pctx, Wo, bo, out, NB * LSEQ, ND, ND, 0, LSEQ);
}